// round 1
// baseline (speedup 1.0000x reference)
#include <cuda_runtime.h>
#include <cstdint>

#define N_DIM 4096
#define NELEM (N_DIM * N_DIM)

// ---------------- device scratch (no runtime allocation allowed) ----------------
__device__ unsigned g_amax_bits[2];          // bit patterns of non-negative floats
__device__ signed char g_qa[NELEM];          // quantized lhs, [M][K] row-major
__device__ signed char g_qb[NELEM];          // quantized rhs^T, [N][K] row-major

// ---------------- helpers ----------------
__device__ __forceinline__ void cp16(void* smem, const void* gmem) {
    unsigned s = (unsigned)__cvta_generic_to_shared(smem);
    asm volatile("cp.async.cg.shared.global [%0], [%1], 16;\n" :: "r"(s), "l"(gmem));
}
__device__ __forceinline__ void cp_commit() {
    asm volatile("cp.async.commit_group;\n");
}
template <int N>
__device__ __forceinline__ void cp_wait() {
    asm volatile("cp.async.wait_group %0;\n" :: "n"(N));
}

__device__ __forceinline__ signed char quant1(float v, float s) {
    float q = rintf(v * s);                 // round-half-even, matches jnp.round
    q = fminf(fmaxf(q, -127.0f), 127.0f);
    return (signed char)(int)q;
}

// ---------------- stage 0: reset ----------------
__global__ void reset_kernel() {
    g_amax_bits[0] = 0u;
    g_amax_bits[1] = 0u;
}

// ---------------- stage 1: abs-max reduction ----------------
__global__ void amax_kernel(const float* __restrict__ x, int sel) {
    int tid = blockIdx.x * blockDim.x + threadIdx.x;
    int stride = gridDim.x * blockDim.x;
    const float4* x4 = (const float4*)x;
    float m = 0.0f;
    for (int i = tid; i < NELEM / 4; i += stride) {
        float4 v = x4[i];
        m = fmaxf(m, fmaxf(fmaxf(fabsf(v.x), fabsf(v.y)),
                           fmaxf(fabsf(v.z), fabsf(v.w))));
    }
    #pragma unroll
    for (int o = 16; o; o >>= 1) m = fmaxf(m, __shfl_xor_sync(0xffffffffu, m, o));
    __shared__ float sm[32];
    int lane = threadIdx.x & 31, w = threadIdx.x >> 5;
    if (lane == 0) sm[w] = m;
    __syncthreads();
    if (w == 0) {
        m = (lane < (int)(blockDim.x >> 5)) ? sm[lane] : 0.0f;
        #pragma unroll
        for (int o = 16; o; o >>= 1) m = fmaxf(m, __shfl_xor_sync(0xffffffffu, m, o));
        if (lane == 0) atomicMax(&g_amax_bits[sel], __float_as_uint(m));
    }
}

// ---------------- stage 2a: quantize lhs (row-major) ----------------
__global__ void quant_lhs_kernel(const float* __restrict__ x) {
    float amax = fmaxf(__uint_as_float(g_amax_bits[0]), 1e-12f);
    float s = 127.0f / amax;
    int tid = blockIdx.x * blockDim.x + threadIdx.x;
    int stride = gridDim.x * blockDim.x;
    const float4* x4 = (const float4*)x;
    char4* q4 = (char4*)g_qa;
    for (int i = tid; i < NELEM / 4; i += stride) {
        float4 v = x4[i];
        char4 q;
        q.x = quant1(v.x, s);
        q.y = quant1(v.y, s);
        q.z = quant1(v.z, s);
        q.w = quant1(v.w, s);
        q4[i] = q;
    }
}

// ---------------- stage 2b: quantize + transpose rhs -> [N][K] ----------------
__global__ void quant_rhs_t_kernel(const float* __restrict__ x) {
    __shared__ signed char tile[32][36];
    float amax = fmaxf(__uint_as_float(g_amax_bits[1]), 1e-12f);
    float s = 127.0f / amax;
    int k0 = blockIdx.y * 32;
    int n0 = blockIdx.x * 32;
    int tx = threadIdx.x;   // 0..31 (n within tile on read)
    int ty = threadIdx.y;   // 0..7
    #pragma unroll
    for (int i = 0; i < 4; i++) {
        int k = ty + i * 8;
        float v = x[(size_t)(k0 + k) * N_DIM + n0 + tx];
        tile[tx][k] = quant1(v, s);   // transposed store: [n][k]
    }
    __syncthreads();
    #pragma unroll
    for (int i = 0; i < 4; i++) {
        int n = ty + i * 8;
        g_qb[(size_t)(n0 + n) * N_DIM + k0 + tx] = tile[n][tx];
    }
}

// ---------------- stage 3: s8 GEMM, mma.sync m16n8k32, 128x128x64 tiles ----------------
#define BM 128
#define BN 128
#define BK 64
#define PAD 80   // padded smem row bytes: (row*20 + tig) mod 32 covers all banks

__global__ __launch_bounds__(256, 1) void gemm_s8_kernel(float* __restrict__ out) {
    __shared__ signed char As[2][BM][PAD];
    __shared__ signed char Bs[2][BN][PAD];

    const int tid = threadIdx.x;
    const int bm = blockIdx.y, bn = blockIdx.x;
    const int warp = tid >> 5, lane = tid & 31;
    const int wm = warp >> 2;          // 0..1  (64 rows each)
    const int wn = warp & 3;           // 0..3  (32 cols each)
    const int group = lane >> 2;       // 0..7
    const int tig = lane & 3;          // 0..3

    int acc[4][4][4];
    #pragma unroll
    for (int a = 0; a < 4; a++)
        #pragma unroll
        for (int b = 0; b < 4; b++)
            #pragma unroll
            for (int c = 0; c < 4; c++) acc[a][b][c] = 0;

    const signed char* gA = g_qa + (size_t)(bm * BM) * N_DIM;
    const signed char* gB = g_qb + (size_t)(bn * BN) * N_DIM;

    const int lrow = tid >> 2;          // 0..63
    const int lcol = (tid & 3) << 4;    // 0,16,32,48
    const int NK = N_DIM / BK;          // 64

    // prologue: load tile 0 into buffer 0
    {
        const signed char* ga = gA + (size_t)lrow * N_DIM + lcol;
        const signed char* gb = gB + (size_t)lrow * N_DIM + lcol;
        cp16(&As[0][lrow][lcol], ga);
        cp16(&As[0][lrow + 64][lcol], ga + (size_t)64 * N_DIM);
        cp16(&Bs[0][lrow][lcol], gb);
        cp16(&Bs[0][lrow + 64][lcol], gb + (size_t)64 * N_DIM);
        cp_commit();
    }

    for (int kt = 0; kt < NK; ++kt) {
        const int buf = kt & 1;
        if (kt + 1 < NK) {
            const int nb = buf ^ 1;
            const size_t ko = (size_t)(kt + 1) * BK;
            const signed char* ga = gA + (size_t)lrow * N_DIM + ko + lcol;
            const signed char* gb = gB + (size_t)lrow * N_DIM + ko + lcol;
            cp16(&As[nb][lrow][lcol], ga);
            cp16(&As[nb][lrow + 64][lcol], ga + (size_t)64 * N_DIM);
            cp16(&Bs[nb][lrow][lcol], gb);
            cp16(&Bs[nb][lrow + 64][lcol], gb + (size_t)64 * N_DIM);
            cp_commit();
            cp_wait<1>();
        } else {
            cp_wait<0>();
        }
        __syncthreads();

        #pragma unroll
        for (int ks = 0; ks < 2; ++ks) {
            const int kb = ks * 32 + tig * 4;
            int af[4][4];
            #pragma unroll
            for (int mf = 0; mf < 4; ++mf) {
                const signed char* p = &As[buf][wm * 64 + mf * 16 + group][kb];
                af[mf][0] = *(const int*)(p);
                af[mf][1] = *(const int*)(p + 8 * PAD);
                af[mf][2] = *(const int*)(p + 16);
                af[mf][3] = *(const int*)(p + 8 * PAD + 16);
            }
            int bf[4][2];
            #pragma unroll
            for (int nf = 0; nf < 4; ++nf) {
                const signed char* p = &Bs[buf][wn * 32 + nf * 8 + group][kb];
                bf[nf][0] = *(const int*)(p);
                bf[nf][1] = *(const int*)(p + 16);
            }
            #pragma unroll
            for (int mf = 0; mf < 4; ++mf) {
                #pragma unroll
                for (int nf = 0; nf < 4; ++nf) {
                    asm volatile(
                        "mma.sync.aligned.m16n8k32.row.col.s32.s8.s8.s32 "
                        "{%0,%1,%2,%3}, {%4,%5,%6,%7}, {%8,%9}, {%0,%1,%2,%3};\n"
                        : "+r"(acc[mf][nf][0]), "+r"(acc[mf][nf][1]),
                          "+r"(acc[mf][nf][2]), "+r"(acc[mf][nf][3])
                        : "r"(af[mf][0]), "r"(af[mf][1]), "r"(af[mf][2]), "r"(af[mf][3]),
                          "r"(bf[nf][0]), "r"(bf[nf][1]));
                }
            }
        }
        __syncthreads();
    }

    // epilogue: dequantize exactly as reference: acc / (ls * rs)
    const float al = fmaxf(__uint_as_float(g_amax_bits[0]), 1e-12f);
    const float ar = fmaxf(__uint_as_float(g_amax_bits[1]), 1e-12f);
    const float ls = 127.0f / al;
    const float rs = 127.0f / ar;
    const float sprod = ls * rs;

    #pragma unroll
    for (int mf = 0; mf < 4; ++mf) {
        #pragma unroll
        for (int nf = 0; nf < 4; ++nf) {
            const int r = bm * BM + wm * 64 + mf * 16 + group;
            const int c = bn * BN + wn * 32 + nf * 8 + tig * 2;
            float* o0 = out + (size_t)r * N_DIM + c;
            float* o1 = o0 + (size_t)8 * N_DIM;
            o0[0] = (float)acc[mf][nf][0] / sprod;
            o0[1] = (float)acc[mf][nf][1] / sprod;
            o1[0] = (float)acc[mf][nf][2] / sprod;
            o1[1] = (float)acc[mf][nf][3] / sprod;
        }
    }
}

// ---------------- launch ----------------
extern "C" void kernel_launch(void* const* d_in, const int* in_sizes, int n_in,
                              void* d_out, int out_size) {
    const float* lhs = (const float*)d_in[0];
    const float* rhs = (const float*)d_in[1];
    float* out = (float*)d_out;

    reset_kernel<<<1, 1>>>();
    amax_kernel<<<512, 256>>>(lhs, 0);
    amax_kernel<<<512, 256>>>(rhs, 1);
    quant_lhs_kernel<<<1024, 256>>>(lhs);
    {
        dim3 grid(N_DIM / 32, N_DIM / 32);
        dim3 block(32, 8);
        quant_rhs_t_kernel<<<grid, block>>>(rhs);
    }
    {
        dim3 grid(N_DIM / BN, N_DIM / BM);
        gemm_s8_kernel<<<grid, 256>>>(out);
    }
}